// round 13
// baseline (speedup 1.0000x reference)
#include <cuda_runtime.h>

#define N_PART 512
#define NK 32
#define NT 10
#define NB 8
#define EPSF 1e-6f
#define LOG2E 1.4426950408889634f
#define TWO_LN2 1.3862943611198906f

// Per-k folded constants: {mu_k, -ig2_k*log2e, w_eff_k, -2*ig2_k*w_eff_k}
__device__ float4 g_cK[NK];
__device__ float g_C;

__device__ __forceinline__ float ex2f(float x) {
    float r; asm("ex2.approx.f32 %0, %1;" : "=f"(r) : "f"(x)); return r;
}
__device__ __forceinline__ float sqrt_ap(float x) {
    float r; asm("sqrt.approx.f32 %0, %1;" : "=f"(r) : "f"(x)); return r;
}

__global__ void prep_kernel(const float* __restrict__ t,
                            const float* __restrict__ mus,
                            const float* __restrict__ nlg,
                            const float* __restrict__ mus_t,
                            const float* __restrict__ nlg_t,
                            const float* __restrict__ W,
                            const float* __restrict__ bias,
                            const float* __restrict__ imp,
                            float* __restrict__ out, int out_total) {
    __shared__ float strbf[NT];
    const int tid = threadIdx.x;
    // Zero the whole output (forces + divergence) so force_kernel can be all-atomic.
    for (int idx = tid; idx < out_total; idx += 256) out[idx] = 0.f;

    if (tid == 0) {
        float tt = t[0];
        float rb[NT];
        float s = 0.f;
        for (int i = 0; i < NT; i++) {
            float g = expf(nlg_t[i]);
            float ig2 = g * g;
            float diff = tt - mus_t[i];
            float e = expf(-diff * diff * ig2);
            rb[i] = e;
            s += e;
        }
        float inv = 1.f / (EPSF + s);
        for (int i = 0; i < NT; i++) strbf[i] = rb[i] * inv;
    }
    __syncthreads();
    if (tid < NK) {
        const int k = tid;
        float w = 0.f;
        for (int ti = 0; ti < NT; ti++) w += W[k * NT + ti] * strbf[ti];
        float g = expf(nlg[k]);
        float ig2 = g * g;
        g_cK[k] = make_float4(mus[k], -ig2 * LOG2E, w, -2.f * ig2 * w);
        float cp = imp[k] * imp[k] * w;
        #pragma unroll
        for (int o = 16; o > 0; o >>= 1) cp += __shfl_down_sync(0xffffffffu, cp, o);
        if (k == 0) {
            float bb = 0.f;
            for (int ti = 0; ti < NT; ti++) bb += bias[ti] * strbf[ti];
            g_C = bb + cp;
        }
    }
}

__global__ __launch_bounds__(128, 6) void force_kernel(const float* __restrict__ x,
                                                       float* __restrict__ f_out,
                                                       float* __restrict__ div_out) {
    __shared__ float sx[N_PART * 3];
    __shared__ float4 sc[NK];
    __shared__ float slab[4 * N_PART * 3];   // per-warp private j-side accumulators
    const int b = blockIdx.y;
    const int tid = threadIdx.x;

    for (int idx = tid; idx < N_PART * 3; idx += 128)
        sx[idx] = x[b * N_PART * 3 + idx];
    for (int idx = tid; idx < 4 * N_PART * 3; idx += 128)
        slab[idx] = 0.f;
    if (tid < NK) sc[tid] = g_cK[tid];
    __syncthreads();

    const float C = g_C;
    const int warp = tid >> 5;
    const int lane = tid & 31;
    const int i = blockIdx.x * 4 + warp;
    float* fb = f_out + b * N_PART * 3;
    float* myslab = slab + warp * N_PART * 3;

    const float xi0 = sx[i * 3 + 0];
    const float xi1 = sx[i * 3 + 1];
    const float xi2 = sx[i * 3 + 2];

    float fx = 0.f, fy = 0.f, fz = 0.f, dv = 0.f;

    // Symmetric pairing over the ring offset delta = (j - i) mod 512.
    // delta in [1,255]: owned by i. delta == 256: owned by the i < 256 side.
    #pragma unroll 1
    for (int jj = 0; jj < 8; jj++) {
        const int delta = 1 + lane + jj * 32;
        const int j = (i + delta) & (N_PART - 1);
        const float dx = xi0 - sx[j * 3 + 0];
        const float dy = xi1 - sx[j * 3 + 1];
        const float dz = xi2 - sx[j * 3 + 2];
        const float d = sqrt_ap(fmaf(dx, dx, fmaf(dy, dy, fmaf(dz, dz, EPSF))));

        float srbf = 0.f, s1 = 0.f, sd = 0.f, s2 = 0.f;
        #pragma unroll 8
        for (int k = 0; k < NK; k++) {
            const float4 c = sc[k];
            const float diff = d - c.x;              // d - mu
            const float e = ex2f(diff * diff * c.y); // exp(-diff^2*ig2) via ex2
            srbf += e;
            s1 = fmaf(e, c.z, s1);                   // sum e * w
            const float p = diff * e;
            sd = fmaf(p, c.y, sd);                   // log2e * (1/2) * sum drbf
            s2 = fmaf(p, c.w, s2);                   // sum drbf * w
        }
        const float rinv = __fdividef(1.f, EPSF + srbf);
        const float q = s1 * rinv;                   // kernels . w
        float fm = q + C;
        float dfm = (s2 - q * (TWO_LN2 * sd)) * rinv;
        // delta == 256 is seen by both sides; keep only the i < 256 owner.
        const float m = (delta == 256 && i >= 256) ? 0.f : 1.f;
        fm *= m;
        dfm *= m;
        const float gx = dx * fm, gy = dy * fm, gz = dz * fm;
        fx += gx; fy += gy; fz += gz;
        dv += fmaf(d, dfm, 3.f * fm);
        // j-side (Newton's third law): accumulate -r*fm into this warp's slab.
        // Lanes map to distinct j within the warp -> no races, stride-3 -> no bank conflicts.
        myslab[j * 3 + 0] -= gx;
        myslab[j * 3 + 1] -= gy;
        myslab[j * 3 + 2] -= gz;
    }

    #pragma unroll
    for (int o = 16; o > 0; o >>= 1) {
        fx += __shfl_down_sync(0xffffffffu, fx, o);
        fy += __shfl_down_sync(0xffffffffu, fy, o);
        fz += __shfl_down_sync(0xffffffffu, fz, o);
        dv += __shfl_down_sync(0xffffffffu, dv, o);
    }
    if (lane == 0) {
        // fold the i-side into this warp's own slab slot (race-free: slab is per-warp)
        myslab[i * 3 + 0] += fx;
        myslab[i * 3 + 1] += fy;
        myslab[i * 3 + 2] += fz;
        // each unordered pair stands for two ordered pairs -> x2; output is -divergence
        atomicAdd(&div_out[b], -2.f * dv);
    }
    __syncthreads();

    // Drain: sum the 4 per-warp slabs and push to global with one batched pass.
    for (int idx = tid; idx < N_PART * 3; idx += 128) {
        float v = slab[idx] + slab[N_PART * 3 + idx]
                + slab[2 * N_PART * 3 + idx] + slab[3 * N_PART * 3 + idx];
        atomicAdd(&fb[idx], v);
    }
}

extern "C" void kernel_launch(void* const* d_in, const int* in_sizes, int n_in,
                              void* d_out, int out_size) {
    const float* t     = (const float*)d_in[0];
    const float* x     = (const float*)d_in[1];
    const float* mus   = (const float*)d_in[2];
    const float* nlg   = (const float*)d_in[3];
    const float* mus_t = (const float*)d_in[4];
    const float* nlg_t = (const float*)d_in[5];
    const float* W     = (const float*)d_in[6];
    const float* bias  = (const float*)d_in[7];
    const float* imp   = (const float*)d_in[8];

    float* out = (float*)d_out;
    float* div_out = out + (out_size - NB);   // forces first, then -divergence per batch

    prep_kernel<<<1, 256>>>(t, mus, nlg, mus_t, nlg_t, W, bias, imp, out, out_size);
    force_kernel<<<dim3(N_PART / 4, NB), 128>>>(x, out, div_out);
}

// round 14
// speedup vs baseline: 1.3191x; 1.3191x over previous
#include <cuda_runtime.h>

#define N_PART 512
#define NK 32
#define NT 10
#define NB 8
#define GX 128          // force blocks per batch
#define EPSF 1e-6f
#define LOG2E 1.4426950408889634f
#define TWO_LN2 1.3862943611198906f

// Scratch: per-(batch,block) force partials and divergence partials.
__device__ float g_part[NB * GX * N_PART * 3];
__device__ float g_dpart[NB * GX];

__device__ __forceinline__ float ex2f(float x) {
    float r; asm("ex2.approx.f32 %0, %1;" : "=f"(r) : "f"(x)); return r;
}
__device__ __forceinline__ float sqrt_ap(float x) {
    float r; asm("sqrt.approx.f32 %0, %1;" : "=f"(r) : "f"(x)); return r;
}

__global__ __launch_bounds__(128, 6) void force_kernel(const float* __restrict__ t,
                                                       const float* __restrict__ mus,
                                                       const float* __restrict__ nlg,
                                                       const float* __restrict__ mus_t,
                                                       const float* __restrict__ nlg_t,
                                                       const float* __restrict__ W,
                                                       const float* __restrict__ bias,
                                                       const float* __restrict__ imp,
                                                       const float* __restrict__ x) {
    __shared__ float sx[N_PART * 3];
    __shared__ float4 sc[NK];
    __shared__ float slab[4 * N_PART * 3];   // per-warp private j-side accumulators
    __shared__ float srb[NT];                // unnormalized time rbfs
    __shared__ float sCv;
    __shared__ float sdvw[4];
    const int b = blockIdx.y;
    const int tid = threadIdx.x;

    for (int idx = tid; idx < N_PART * 3; idx += 128)
        sx[idx] = x[b * N_PART * 3 + idx];
    for (int idx = tid; idx < 4 * N_PART * 3; idx += 128)
        slab[idx] = 0.f;
    if (tid < NT) {
        float g = expf(nlg_t[tid]);
        float diff = t[0] - mus_t[tid];
        srb[tid] = expf(-diff * diff * g * g);
    }
    __syncthreads();

    if (tid < NK) {
        float s = 0.f;
        #pragma unroll
        for (int ti = 0; ti < NT; ti++) s += srb[ti];
        const float inv = 1.f / (EPSF + s);
        float w = 0.f;
        #pragma unroll
        for (int ti = 0; ti < NT; ti++) w += W[tid * NT + ti] * srb[ti];
        w *= inv;
        float g = expf(nlg[tid]);
        float ig2 = g * g;
        sc[tid] = make_float4(mus[tid], -ig2 * LOG2E, w, -2.f * ig2 * w);
        float cp = imp[tid] * imp[tid] * w;
        #pragma unroll
        for (int o = 16; o > 0; o >>= 1) cp += __shfl_down_sync(0xffffffffu, cp, o);
        if (tid == 0) {
            float bb = 0.f;
            #pragma unroll
            for (int ti = 0; ti < NT; ti++) bb += bias[ti] * srb[ti];
            sCv = bb * inv + cp;
        }
    }
    __syncthreads();

    const float C = sCv;
    const int warp = tid >> 5;
    const int lane = tid & 31;
    const int i = blockIdx.x * 4 + warp;
    float* myslab = slab + warp * N_PART * 3;

    const float xi0 = sx[i * 3 + 0];
    const float xi1 = sx[i * 3 + 1];
    const float xi2 = sx[i * 3 + 2];

    float fx = 0.f, fy = 0.f, fz = 0.f, dv = 0.f;

    // Symmetric pairing over the ring offset delta = (j - i) mod 512.
    // delta in [1,255]: owned by i. delta == 256: owned by the i < 256 side.
    #pragma unroll 1
    for (int jj = 0; jj < 8; jj++) {
        const int delta = 1 + lane + jj * 32;
        const int j = (i + delta) & (N_PART - 1);
        const float dx = xi0 - sx[j * 3 + 0];
        const float dy = xi1 - sx[j * 3 + 1];
        const float dz = xi2 - sx[j * 3 + 2];
        const float d = sqrt_ap(fmaf(dx, dx, fmaf(dy, dy, fmaf(dz, dz, EPSF))));

        float srbf = 0.f, s1 = 0.f, sd = 0.f, s2 = 0.f;
        #pragma unroll 8
        for (int k = 0; k < NK; k++) {
            const float4 c = sc[k];
            const float diff = d - c.x;              // d - mu
            const float e = ex2f(diff * diff * c.y); // exp(-diff^2*ig2) via ex2
            srbf += e;
            s1 = fmaf(e, c.z, s1);                   // sum e * w
            const float p = diff * e;
            sd = fmaf(p, c.y, sd);                   // log2e * (1/2) * sum drbf
            s2 = fmaf(p, c.w, s2);                   // sum drbf * w
        }
        const float rinv = __fdividef(1.f, EPSF + srbf);
        const float q = s1 * rinv;                   // kernels . w
        float fm = q + C;
        float dfm = (s2 - q * (TWO_LN2 * sd)) * rinv;
        // delta == 256 is seen by both sides; keep only the i < 256 owner.
        const float m = (delta == 256 && i >= 256) ? 0.f : 1.f;
        fm *= m;
        dfm *= m;
        const float gx = dx * fm, gy = dy * fm, gz = dz * fm;
        fx += gx; fy += gy; fz += gz;
        dv += fmaf(d, dfm, 3.f * fm);
        // j-side (Newton's third law): accumulate -r*fm into this warp's slab.
        myslab[j * 3 + 0] -= gx;
        myslab[j * 3 + 1] -= gy;
        myslab[j * 3 + 2] -= gz;
    }

    #pragma unroll
    for (int o = 16; o > 0; o >>= 1) {
        fx += __shfl_down_sync(0xffffffffu, fx, o);
        fy += __shfl_down_sync(0xffffffffu, fy, o);
        fz += __shfl_down_sync(0xffffffffu, fz, o);
        dv += __shfl_down_sync(0xffffffffu, dv, o);
    }
    if (lane == 0) {
        myslab[i * 3 + 0] += fx;
        myslab[i * 3 + 1] += fy;
        myslab[i * 3 + 2] += fz;
        sdvw[warp] = dv;
    }
    __syncthreads();

    // Drain: sum the 4 per-warp slabs into this block's partial (plain stores).
    float* part = g_part + (b * GX + blockIdx.x) * N_PART * 3;
    for (int idx = tid; idx < N_PART * 3; idx += 128)
        part[idx] = slab[idx] + slab[N_PART * 3 + idx]
                  + slab[2 * N_PART * 3 + idx] + slab[3 * N_PART * 3 + idx];
    if (tid == 0)
        g_dpart[b * GX + blockIdx.x] = -2.f * (sdvw[0] + sdvw[1] + sdvw[2] + sdvw[3]);
}

// grid: (7, NB). x<6: 256 force elements each. x==6: divergence.
__global__ __launch_bounds__(256) void reduce_kernel(float* __restrict__ out) {
    const int b = blockIdx.y;
    const int tid = threadIdx.x;
    if (blockIdx.x < 6) {
        const int idx = blockIdx.x * 256 + tid;
        const float* base = g_part + b * GX * N_PART * 3 + idx;
        float s0 = 0.f, s1 = 0.f;
        #pragma unroll 8
        for (int k = 0; k < GX; k += 2) {
            s0 += base[k * N_PART * 3];
            s1 += base[(k + 1) * N_PART * 3];
        }
        out[b * N_PART * 3 + idx] = s0 + s1;
    } else {
        float v = (tid < GX) ? g_dpart[b * GX + tid] : 0.f;
        #pragma unroll
        for (int o = 16; o > 0; o >>= 1) v += __shfl_down_sync(0xffffffffu, v, o);
        __shared__ float sw[8];
        if ((tid & 31) == 0) sw[tid >> 5] = v;
        __syncthreads();
        if (tid == 0)
            out[NB * N_PART * 3 + b] = sw[0] + sw[1] + sw[2] + sw[3];
    }
}

extern "C" void kernel_launch(void* const* d_in, const int* in_sizes, int n_in,
                              void* d_out, int out_size) {
    const float* t     = (const float*)d_in[0];
    const float* x     = (const float*)d_in[1];
    const float* mus   = (const float*)d_in[2];
    const float* nlg   = (const float*)d_in[3];
    const float* mus_t = (const float*)d_in[4];
    const float* nlg_t = (const float*)d_in[5];
    const float* W     = (const float*)d_in[6];
    const float* bias  = (const float*)d_in[7];
    const float* imp   = (const float*)d_in[8];

    float* out = (float*)d_out;

    force_kernel<<<dim3(GX, NB), 128>>>(t, mus, nlg, mus_t, nlg_t, W, bias, imp, x);
    reduce_kernel<<<dim3(7, NB), 256>>>(out);
}